// round 9
// baseline (speedup 1.0000x reference)
#include <cuda_runtime.h>
#include <math.h>

#define SIMS 64
#define SD 65536            // 2^16 state dim
#define PI_F 3.14159265358979323846f
#define INV_SQRT2 0.70710678118654752440f

typedef unsigned long long ull;

// ---------------- device scratch (static, no allocation) ----------------
__device__ __align__(16) float2 g_state[SIMS * SD];   // 32 MB
__device__ float g_partial[SIMS][16][16];             // per-tile Z partials

// ---------------- packed f32x2 helpers ----------------
__device__ __forceinline__ ull pk2(float lo, float hi) {
    ull r; asm("mov.b64 %0, {%1, %2};" : "=l"(r) : "f"(lo), "f"(hi)); return r;
}
__device__ __forceinline__ void up2(ull v, float& lo, float& hi) {
    asm("mov.b64 {%0, %1}, %2;" : "=f"(lo), "=f"(hi) : "l"(v));
}
__device__ __forceinline__ ull mul2(ull a, ull b) {
    ull r; asm("mul.rn.f32x2 %0, %1, %2;" : "=l"(r) : "l"(a), "l"(b)); return r;
}
__device__ __forceinline__ ull fma2(ull a, ull b, ull c) {
    ull r; asm("fma.rn.f32x2 %0, %1, %2, %3;" : "=l"(r) : "l"(a), "l"(b), "l"(c)); return r;
}

// RY butterfly on register-index bit qb, packed (re,im) per reg.
__device__ __forceinline__ void bfp(ull a[16], int qb, ull c2, ull s2, ull ns2) {
#pragma unroll
    for (int p = 0; p < 8; p++) {
        const int j0 = ((p >> qb) << (qb + 1)) | (p & ((1 << qb) - 1));
        const int j1 = j0 | (1 << qb);
        const ull n0 = fma2(ns2, a[j1], mul2(c2, a[j0]));   // c*a0 - s*a1
        const ull n1 = fma2(s2, a[j0], mul2(c2, a[j1]));    // s*a0 + c*a1
        a[j0] = n0; a[j1] = n1;
    }
}

// uniform smem swizzle (8B units): 2-way worst-case conflicts both directions
__device__ __forceinline__ int swz(int e) { return e ^ ((e >> 4) & 15); }

// ======================================================================
// K1: build init product state * D0, RY_A on qubits 0..11 (3 residencies,
//     2 smem transposes), store canonical layout.
// Residency R0: regs=q0..3, lane bits0..3=q4..7, lane bit4=q8, warp=q9..11.
// Residency R1: regs=q4..7 (same lane/warp otherwise).
// Residency R2: regs=q8..11, thread t bits = q0..7 (canonical).
// ======================================================================
__global__ void __launch_bounds__(256) k_pass1(const float* __restrict__ x,
                                               const float* __restrict__ wcrz,
                                               const float* __restrict__ wry,
                                               const float* __restrict__ scale) {
    const int sim = blockIdx.x >> 4;
    const int tile = blockIdx.x & 15;
    const int t = threadIdx.x, l = t & 31, w = t >> 5;
    __shared__ ull sbuf[4096];          // 32 KB transpose buffer
    __shared__ float2 A0s[512];         // CRZ L0, controls q0..7 (idx bits q0..8)
    __shared__ float2 sB0[2][16];       // CRZ L0, controls q8..15 ([q0][q8..11]); tile folded
    __shared__ ull c2s[12], s2s[12], ns2s[12];
    __shared__ float TL4lo[16], TL4hi[16], TH4lo[16];
    __shared__ float v0s[16], v1s[16], sw[32];
    __shared__ float THhi;

    if (t < 32) sw[t] = 0.5f * wcrz[t];
    if (t < 16) {
        const int q = t, bb = sim >> 3, p = sim & 7;
        const float xv = x[bb * 128 + (q >> 2) * 32 + p * 4 + (q & 3)];
        const float enc = tanhf(xv * scale[0]) * PI_F;
        float se, ce; sincosf(enc * 0.5f, &se, &ce);
        v0s[q] = (ce - se) * INV_SQRT2;     // RY(enc)*H|0>
        v1s[q] = (ce + se) * INV_SQRT2;
        if (q < 12) {
            float sA, cA; sincosf((wry[q] + enc) * 0.5f, &sA, &cA);  // merged RY(w0+enc)
            c2s[q] = pk2(cA, cA); s2s[q] = pk2(sA, sA); ns2s[q] = pk2(-sA, -sA);
        }
    }
    __syncthreads();
    if (t < 16) {
        const int m = t;
        float plo = 1.f, pmid = 1.f, phl = 1.f;
#pragma unroll
        for (int q = 0; q < 4; q++) {
            plo  *= ((m >> q) & 1) ? v1s[q]     : v0s[q];
            pmid *= ((m >> q) & 1) ? v1s[4 + q] : v0s[4 + q];
            phl  *= ((m >> q) & 1) ? v1s[8 + q] : v0s[8 + q];
        }
        TL4lo[m] = plo; TL4hi[m] = pmid; TH4lo[m] = phl;
    }
    if (t == 0) {
        float ph = 1.f;
#pragma unroll
        for (int q = 0; q < 4; q++) ph *= ((tile >> q) & 1) ? v1s[12 + q] : v0s[12 + q];
        THhi = ph;
    }
    // A0 table: controls q0..7, target q+1 (bits 1..8)
    for (int i = t; i < 512; i += 256) {
        float a = 0.f;
#pragma unroll
        for (int q = 0; q < 8; q++)
            if ((i >> q) & 1) a += ((i >> (q + 1)) & 1) ? sw[q] : -sw[q];
        float s, c; sincosf(a, &s, &c);
        A0s[i] = make_float2(c, s);
    }
    // B0 slice: controls q8..15, targets (q+1)&15 ; tile fixes q12..15
    if (t < 32) {
        const int q0b = t >> 4, m = t & 15;
        const int i8 = m | (tile << 4);           // bits 0..7 = q8..15
        float a = 0.f;
#pragma unroll
        for (int q = 8; q < 16; q++) {
            if ((i8 >> (q - 8)) & 1) {
                const int tb = (q == 15) ? q0b : ((i8 >> (q - 7)) & 1);
                a += tb ? sw[q] : -sw[q];
            }
        }
        float s, c; sincosf(a, &s, &c);
        sB0[q0b][m] = make_float2(c, s);
    }
    __syncthreads();

    // init amplitudes in R0
    const int m8 = (l >> 4) | (w << 1);           // q8..11
    const float K = TL4hi[l & 15] * TH4lo[m8] * THhi;
    const float2 pb0 = sB0[0][m8];
    const float2 pb1 = sB0[1][m8];
    const int ebase = ((l & 15) << 4) | ((l >> 4) << 8);
    ull a[16];
#pragma unroll
    for (int j = 0; j < 16; j++) {
        const float2 pa = A0s[ebase | j];
        const float2 pb = (j & 1) ? pb1 : pb0;
        const float cr = pa.x * pb.x - pa.y * pb.y;
        const float ci = pa.x * pb.y + pa.y * pb.x;
        const float amp = TL4lo[j] * K;
        a[j] = pk2(amp * cr, amp * ci);
    }
    // R0: qubits 0..3
#pragma unroll
    for (int qb = 0; qb < 4; qb++) bfp(a, qb, c2s[qb], s2s[qb], ns2s[qb]);
    // T1: R0 -> R1
#pragma unroll
    for (int j = 0; j < 16; j++) sbuf[swz((w << 9) | (l << 4) | j)] = a[j];
    __syncthreads();
#pragma unroll
    for (int jp = 0; jp < 16; jp++)
        a[jp] = sbuf[swz((w << 9) | ((l >> 4) << 8) | (jp << 4) | (l & 15))];
    // R1: qubits 4..7
#pragma unroll
    for (int qb = 0; qb < 4; qb++) bfp(a, qb, c2s[4 + qb], s2s[4 + qb], ns2s[4 + qb]);
    __syncthreads();
    // T2: R1 -> R2
#pragma unroll
    for (int jp = 0; jp < 16; jp++)
        sbuf[swz((w << 9) | ((l >> 4) << 8) | (jp << 4) | (l & 15))] = a[jp];
    __syncthreads();
#pragma unroll
    for (int j = 0; j < 16; j++) a[j] = sbuf[swz((j << 8) | t)];
    // R2: qubits 8..11
#pragma unroll
    for (int qb = 0; qb < 4; qb++) bfp(a, qb, c2s[8 + qb], s2s[8 + qb], ns2s[8 + qb]);
    // store canonical
    ull* st = reinterpret_cast<ull*>(g_state + sim * SD + (tile << 12));
#pragma unroll
    for (int j = 0; j < 16; j++) st[(j << 8) | t] = a[j];
}

// ======================================================================
// K2: RY_A(12..15), D1 (A1 x B1 split), RY_B(12..15). k-slot = q12..15.
// ======================================================================
__global__ void __launch_bounds__(256) k_pass2(const float* __restrict__ x,
                                               const float* __restrict__ wcrz,
                                               const float* __restrict__ wry,
                                               const float* __restrict__ scale) {
    const int sim = blockIdx.x >> 4;
    const int blk = blockIdx.x & 15;
    const int t = threadIdx.x;
    const int low12 = (blk << 8) | t;
    __shared__ float2 sB1[64];                    // [k][q0..1]
    __shared__ ull cA2[4], sA2[4], nsA2[4], cB2[4], sB2p[4], nsB2[4];
    __shared__ float sw1[16];
    if (t < 16) sw1[t] = 0.5f * wcrz[16 + t];
    if (t < 4) {
        const int q = 12 + t, bb = sim >> 3, p = sim & 7;
        const float xv = x[bb * 128 + 3 * 32 + p * 4 + t];
        const float enc = tanhf(xv * scale[0]) * PI_F;
        float sA, cA; sincosf((wry[q] + enc) * 0.5f, &sA, &cA);
        cA2[t] = pk2(cA, cA); sA2[t] = pk2(sA, sA); nsA2[t] = pk2(-sA, -sA);
        float sB, cB; sincosf(wry[16 + q] * 0.5f, &sB, &cB);
        cB2[t] = pk2(cB, cB); sB2p[t] = pk2(sB, sB); nsB2[t] = pk2(-sB, -sB);
    }
    __syncthreads();
    // B1 slice: controls q8..15, targets (q+2)&15; idx bits 0..3=q8..11(blk),
    // 4..7=q12..15(k), 8..9=q0..1
    if (t < 64) {
        const int k = t >> 2, c2b = t & 3;
        const int i = blk | (k << 4) | (c2b << 8);
        float a = 0.f;
#pragma unroll
        for (int q = 8; q < 16; q++)
            if ((i >> (q - 8)) & 1) a += ((i >> (q - 6)) & 1) ? sw1[q] : -sw1[q];
        float s, c; sincosf(a, &s, &c);
        sB1[t] = make_float2(c, s);
    }
    // A1 per thread: controls q0..7, target q+2 (bits 2..9)
    const int i10 = low12 & 1023;
    float aa = 0.f;
#pragma unroll
    for (int q = 0; q < 8; q++)
        if ((i10 >> q) & 1) aa += ((i10 >> (q + 2)) & 1) ? sw1[q] : -sw1[q];
    float pay, pax; sincosf(aa, &pay, &pax);      // (cos, sin) = (pax, pay)
    __syncthreads();

    ull* st = reinterpret_cast<ull*>(g_state + sim * SD);
    ull a[16];
#pragma unroll
    for (int k = 0; k < 16; k++) a[k] = st[(k << 12) | low12];
    // RY_A qubits 12..15
#pragma unroll
    for (int qb = 0; qb < 4; qb++) bfp(a, qb, cA2[qb], sA2[qb], nsA2[qb]);
    // D1 phase
    const int c2b = t & 3;
#pragma unroll
    for (int k = 0; k < 16; k++) {
        float xr, yi; up2(a[k], xr, yi);
        const float2 pb = sB1[(k << 2) | c2b];
        const float cr = pax * pb.x - pay * pb.y;
        const float ci = pax * pb.y + pay * pb.x;
        a[k] = pk2(xr * cr - yi * ci, xr * ci + yi * cr);
    }
    // RY_B qubits 12..15
#pragma unroll
    for (int qb = 0; qb < 4; qb++) bfp(a, qb, cB2[qb], sB2p[qb], nsB2[qb]);
#pragma unroll
    for (int k = 0; k < 16; k++) st[(k << 12) | low12] = a[k];
}

// ======================================================================
// K3: RY_B qubits 0..11 (R2 -> R1 -> R0, 2 transposes) + measurement.
// ======================================================================
__global__ void __launch_bounds__(256) k_pass3(const float* __restrict__ wry) {
    const int sim = blockIdx.x >> 4;
    const int tile = blockIdx.x & 15;
    const int t = threadIdx.x, l = t & 31, w = t >> 5;
    __shared__ ull sbuf[4096];
    __shared__ ull c2s[12], s2s[12], ns2s[12];
    __shared__ float wred[8][10];
    if (t < 12) {
        float sB, cB; sincosf(wry[16 + t] * 0.5f, &sB, &cB);
        c2s[t] = pk2(cB, cB); s2s[t] = pk2(sB, sB); ns2s[t] = pk2(-sB, -sB);
    }
    __syncthreads();
    const ull* stg = reinterpret_cast<const ull*>(g_state + sim * SD + (tile << 12));
    ull a[16];
#pragma unroll
    for (int j = 0; j < 16; j++) a[j] = stg[(j << 8) | t];
    // R2: qubits 8..11
#pragma unroll
    for (int qb = 0; qb < 4; qb++) bfp(a, qb, c2s[8 + qb], s2s[8 + qb], ns2s[8 + qb]);
    // T: R2 -> R1
#pragma unroll
    for (int j = 0; j < 16; j++) sbuf[swz((j << 8) | t)] = a[j];
    __syncthreads();
#pragma unroll
    for (int jp = 0; jp < 16; jp++)
        a[jp] = sbuf[swz((w << 9) | ((l >> 4) << 8) | (jp << 4) | (l & 15))];
    // R1: qubits 4..7
#pragma unroll
    for (int qb = 0; qb < 4; qb++) bfp(a, qb, c2s[4 + qb], s2s[4 + qb], ns2s[4 + qb]);
    __syncthreads();
    // T: R1 -> R0
#pragma unroll
    for (int jp = 0; jp < 16; jp++)
        sbuf[swz((w << 9) | ((l >> 4) << 8) | (jp << 4) | (l & 15))] = a[jp];
    __syncthreads();
#pragma unroll
    for (int j = 0; j < 16; j++) a[j] = sbuf[swz((w << 9) | (l << 4) | j)];
    // R0: qubits 0..3
#pragma unroll
    for (int qb = 0; qb < 4; qb++) bfp(a, qb, c2s[qb], s2s[qb], ns2s[qb]);

    // measurement in R0: j=q0..3, l bits0..3=q4..7, l bit4=q8, w=q9..11, tile=q12..15
    float z0 = 0.f, z1 = 0.f, z2 = 0.f, z3 = 0.f, pt = 0.f;
#pragma unroll
    for (int j = 0; j < 16; j++) {
        float xr, yi; up2(a[j], xr, yi);
        const float p = fmaf(yi, yi, xr * xr);
        pt += p;
        z0 += (j & 1) ? -p : p;
        z1 += (j & 2) ? -p : p;
        z2 += (j & 4) ? -p : p;
        z3 += (j & 8) ? -p : p;
    }
    float v[10];
    v[0] = z0; v[1] = z1; v[2] = z2; v[3] = z3;
#pragma unroll
    for (int q = 0; q < 4; q++) v[4 + q] = ((l >> q) & 1) ? -pt : pt;   // q4..7
    v[8] = (l & 16) ? -pt : pt;                                          // q8
    v[9] = pt;
#pragma unroll
    for (int k = 0; k < 10; k++) {
        float xv = v[k];
#pragma unroll
        for (int o = 16; o > 0; o >>= 1) xv += __shfl_xor_sync(0xffffffffu, xv, o);
        v[k] = xv;
    }
    if ((t & 31) == 0) {
#pragma unroll
        for (int k = 0; k < 10; k++) wred[w][k] = v[k];
    }
    __syncthreads();
    if (t < 16) {
        float s = 0.f;
        if (t < 9) {
#pragma unroll
            for (int w2 = 0; w2 < 8; w2++) s += wred[w2][t];
        } else if (t < 12) {
#pragma unroll
            for (int w2 = 0; w2 < 8; w2++)
                s += ((w2 >> (t - 9)) & 1) ? -wred[w2][9] : wred[w2][9];
        } else {
            float tot = 0.f;
#pragma unroll
            for (int w2 = 0; w2 < 8; w2++) tot += wred[w2][9];
            s = ((tile >> (t - 12)) & 1) ? -tot : tot;
        }
        g_partial[sim][tile][t] = s;
    }
}

// ---------------- K4: deterministic reduce, clip, permute to output ----------------
__global__ void k_out(float* __restrict__ out) {
    const int i = threadIdx.x;   // 1024 = 64 sims * 16 qubits
    const int sim = i >> 4, q = i & 15;
    float s = 0.f;
#pragma unroll
    for (int tl = 0; tl < 16; tl++) s += g_partial[sim][tl][q];
    s = fminf(1.0f, fmaxf(-1.0f, s));
    const int bb = sim >> 3, p = sim & 7, h = q >> 2, ww = q & 3;
    out[bb * 128 + h * 32 + p * 4 + ww] = s;
}

// ---------------- launch ----------------
extern "C" void kernel_launch(void* const* d_in, const int* in_sizes, int n_in,
                              void* d_out, int out_size) {
    const float* x     = (const float*)d_in[0];
    const float* wcrz  = (const float*)d_in[1];
    const float* wry   = (const float*)d_in[2];
    const float* scale = (const float*)d_in[3];
    float* out = (float*)d_out;

    k_pass1<<<SIMS * 16, 256>>>(x, wcrz, wry, scale);
    k_pass2<<<SIMS * 16, 256>>>(x, wcrz, wry, scale);
    k_pass3<<<SIMS * 16, 256>>>(wry);
    k_out<<<1, 1024>>>(out);
}

// round 10
// speedup vs baseline: 1.0451x; 1.0451x over previous
#include <cuda_runtime.h>
#include <math.h>

#define SIMS 64
#define SD 65536            // 2^16 state dim
#define PI_F 3.14159265358979323846f
#define INV_SQRT2 0.70710678118654752440f

// ---------------- device scratch (static, no allocation) ----------------
__device__ __align__(16) float2 g_state[SIMS * SD];   // 32 MB (L2-resident)
__device__ float2 g_A0[512];    // CRZ layer0, controls q0..7  (idx bits 0..8 = qubit bits 0..8)
__device__ float2 g_B0[512];    // CRZ layer0, controls q8..15 (idx bits 0..7 = q8..15, bit 8 = q0)
__device__ float2 g_A1[1024];   // CRZ layer1, controls q0..7  (idx bits 0..9 = qubit bits 0..9)
__device__ float2 g_B1[1024];   // CRZ layer1, controls q8..15 (idx bits 0..7 = q8..15, bits 8..9 = q0..1)
__device__ float g_TL[SIMS][256];                     // product tables (qubits 0..7)
__device__ float g_TH[SIMS][256];                     // product tables (qubits 8..15)
__device__ float g_cA[SIMS][16], g_sA[SIMS][16];      // cos/sin((w_ry0+enc)/2)
__device__ float g_cw[16], g_sw[16];                  // cos/sin(w_ry1) FULL angle (for conjugated measurement)
__device__ float g_Z[SIMS][16][16];                   // per-tile <Z_q> partials
__device__ float g_X[SIMS][16][12];                   // per-tile <X_q> partials, q=0..11
__device__ float g_X2[SIMS][16][4];                   // per-blk  <X_q> partials, q=12..15 (from pass2)
__device__ unsigned g_ctr;

__device__ __forceinline__ float wsum(float x) {
#pragma unroll
    for (int o = 16; o > 0; o >>= 1) x += __shfl_xor_sync(0xffffffffu, x, o);
    return x;
}

// ---------------- prep: per-sim params + split CRZ phase tables ----------------
__global__ void k_prep(const float* __restrict__ x,
                       const float* __restrict__ wcrz,
                       const float* __restrict__ wry,
                       const float* __restrict__ scale) {
    const int blk = blockIdx.x;
    const int t = threadIdx.x;         // 256 threads
    if (blk == 0 && t == 200) g_ctr = 0;
    if (blk < SIMS) {
        const int sim = blk;
        __shared__ float v0[16], v1[16];
        if (t < 16) {
            const int q = t;
            const int bb = sim >> 3, p = sim & 7;
            const float xv = x[bb * 128 + (q >> 2) * 32 + p * 4 + (q & 3)];
            const float enc = tanhf(xv * scale[0]) * PI_F;
            float se, ce;
            sincosf(enc * 0.5f, &se, &ce);
            v0[q] = (ce - se) * INV_SQRT2;
            v1[q] = (ce + se) * INV_SQRT2;
            float sA, cA;
            sincosf((wry[q] + enc) * 0.5f, &sA, &cA);   // merged RY(w_ry0 + enc)
            g_cA[sim][q] = cA;  g_sA[sim][q] = sA;
            if (sim == 0) {
                float sB, cB;
                sincosf(wry[16 + q], &sB, &cB);          // FULL angle
                g_cw[q] = cB;  g_sw[q] = sB;
            }
        }
        __syncthreads();
        const int m = t;
        float pl = 1.0f, ph = 1.0f;
#pragma unroll
        for (int q = 0; q < 8; q++) {
            pl *= ((m >> q) & 1) ? v1[q] : v0[q];
            ph *= ((m >> q) & 1) ? v1[8 + q] : v0[8 + q];
        }
        g_TL[sim][m] = pl;
        g_TH[sim][m] = ph;
    } else {
        // table builder blocks: blk = 64..67
        __shared__ float w[32];
        if (t < 32) w[t] = 0.5f * wcrz[t];
        __syncthreads();
        const int which = blk - SIMS;
        if (which == 0) {          // A0: controls q0..7, targets q+1 (bits 1..8)
            for (int i = t; i < 512; i += 256) {
                float a = 0.0f;
#pragma unroll
                for (int q = 0; q < 8; q++)
                    if ((i >> q) & 1) a += ((i >> (q + 1)) & 1) ? w[q] : -w[q];
                float s, c; sincosf(a, &s, &c);
                g_A0[i] = make_float2(c, s);
            }
        } else if (which == 1) {   // B0: controls q8..15, targets q+1 mod 16
            for (int i = t; i < 512; i += 256) {
                float a = 0.0f;
#pragma unroll
                for (int q = 8; q < 16; q++) {
                    if ((i >> (q - 8)) & 1) {
                        const int tq = (q + 1) & 15;
                        const int tb = (tq == 0) ? ((i >> 8) & 1) : ((i >> (tq - 8)) & 1);
                        a += tb ? w[q] : -w[q];
                    }
                }
                float s, c; sincosf(a, &s, &c);
                g_B0[i] = make_float2(c, s);
            }
        } else if (which == 2) {   // A1: controls q0..7, targets q+2 (bits 2..9)
            for (int i = t; i < 1024; i += 256) {
                float a = 0.0f;
#pragma unroll
                for (int q = 0; q < 8; q++)
                    if ((i >> q) & 1) a += ((i >> (q + 2)) & 1) ? w[16 + q] : -w[16 + q];
                float s, c; sincosf(a, &s, &c);
                g_A1[i] = make_float2(c, s);
            }
        } else {                   // B1: controls q8..15, targets q+2 mod 16
            for (int i = t; i < 1024; i += 256) {
                float a = 0.0f;
#pragma unroll
                for (int q = 8; q < 16; q++) {
                    if ((i >> (q - 8)) & 1) {
                        const int tq = (q + 2) & 15;
                        const int tb = (tq >= 8) ? ((i >> (tq - 8)) & 1) : ((i >> (8 + tq)) & 1);
                        a += tb ? w[16 + q] : -w[16 + q];
                    }
                }
                float s, c; sincosf(a, &s, &c);
                g_B1[i] = make_float2(c, s);
            }
        }
    }
}

// ---------------- butterfly helpers ----------------
__device__ __forceinline__ void bf_regs(float2 a[16], int qb, float c, float s) {
#pragma unroll
    for (int p = 0; p < 8; p++) {
        const int j0 = ((p >> qb) << (qb + 1)) | (p & ((1 << qb) - 1));
        const int j1 = j0 | (1 << qb);
        const float r0 = c * a[j0].x - s * a[j1].x;
        const float r1 = s * a[j0].x + c * a[j1].x;
        const float i0 = c * a[j0].y - s * a[j1].y;
        const float i1 = s * a[j0].y + c * a[j1].y;
        a[j0].x = r0; a[j1].x = r1; a[j0].y = i0; a[j1].y = i1;
    }
}

__device__ __forceinline__ void bf_shfl(float2 a[16], const float* sc, const float* ss, int lane) {
#pragma unroll
    for (int q = 0; q < 5; q++) {
        const float c = sc[q], s = ss[q];
        const int m = 1 << q;
        const float sgn = (lane & m) ? s : -s;
#pragma unroll
        for (int j = 0; j < 16; j++) {
            const float ox = __shfl_xor_sync(0xffffffffu, a[j].x, m);
            const float oy = __shfl_xor_sync(0xffffffffu, a[j].y, m);
            a[j].x = fmaf(sgn, ox, c * a[j].x);
            a[j].y = fmaf(sgn, oy, c * a[j].y);
        }
    }
}

// ---------------- K1: init * D0 (split tables), RY_A on qubits 0..11 ----------------
// Layout L1: t bits 0..7 <-> qubits 0..7 (lane=0..4, warp=5..7), regs j <-> qubits 8..11.
// Layout L1': lane <-> 0..4, warp w <-> 8..10, regs jp: bits0..2 <-> 5..7, bit3 <-> 11.
__global__ void __launch_bounds__(256) k_pass1() {
    const int sim = blockIdx.x >> 4;
    const int tile = blockIdx.x & 15;
    const int t = threadIdx.x;
    const int lane = t & 31;
    const int w = t >> 5;
    __shared__ float2 sbuf[4096];
    __shared__ float sc[16], ss[16], sTH[16];
    __shared__ float2 sB0[2][16];
    if (t < 16) {
        sc[t] = g_cA[sim][t];
        ss[t] = g_sA[sim][t];
        sTH[t] = g_TH[sim][(tile << 4) | t];
    }
    if (t < 32) {
        const int b0 = t >> 4, j = t & 15;
        sB0[b0][j] = g_B0[(tile << 4) | j | (b0 << 8)];
    }
    __syncthreads();
    const float tl = g_TL[sim][t];
    const float2 pa0 = g_A0[t];
    const float2 pa1 = g_A0[t | 256];
    const int myb0 = t & 1;
    float2 a[16];
#pragma unroll
    for (int j = 0; j < 16; j++) {
        const float2 pa = (j & 1) ? pa1 : pa0;       // A0 bit8 = qubit8 = j bit0
        const float2 pb = sB0[myb0][j];
        const float cr = pa.x * pb.x - pa.y * pb.y;  // e^{i(A0+B0)}
        const float ci = pa.x * pb.y + pa.y * pb.x;
        const float amp = tl * sTH[j];
        a[j] = make_float2(amp * cr, amp * ci);
    }
#pragma unroll
    for (int qb = 0; qb < 4; qb++) bf_regs(a, qb, sc[8 + qb], ss[8 + qb]);
    bf_shfl(a, sc, ss, lane);
#pragma unroll
    for (int j = 0; j < 16; j++) sbuf[(j << 8) | t] = a[j];
    __syncthreads();
    float2 b[16];
#pragma unroll
    for (int jp = 0; jp < 16; jp++) {
        const int oj = w | (jp & 8);
        const int ow = jp & 7;
        b[jp] = sbuf[(oj << 8) | (ow << 5) | lane];
    }
#pragma unroll
    for (int qb = 0; qb < 3; qb++) bf_regs(b, qb, sc[5 + qb], ss[5 + qb]);
    float2* st = g_state + sim * SD + (tile << 12);
#pragma unroll
    for (int jp = 0; jp < 16; jp++)
        st[lane | ((jp & 7) << 5) | (w << 8) | ((jp & 8) << 8)] = b[jp];
}

// ---------------- K2: RY_A(12..15), D1, measure X(12..15), store psi1 ----------------
__global__ void __launch_bounds__(256) k_pass2() {
    const int sim = blockIdx.x >> 4;
    const int blk = blockIdx.x & 15;
    const int t = threadIdx.x;
    const int low12 = (blk << 8) | t;
    __shared__ float2 sB1[64];           // [k][q0..1]
    __shared__ float scA[4], ssA[4];
    __shared__ float wredX[8][4];
    if (t < 64) {
        const int k = t >> 2, c2 = t & 3;
        sB1[t] = g_B1[blk | (k << 4) | (c2 << 8)];
    }
    if (t < 4) {
        scA[t] = g_cA[sim][12 + t]; ssA[t] = g_sA[sim][12 + t];
    }
    __syncthreads();
    const float2 pa = g_A1[low12 & 1023];
    float2* st = g_state + sim * SD;
    float2 a[16];
#pragma unroll
    for (int k = 0; k < 16; k++) a[k] = st[(k << 12) | low12];
    // RY_A qubits 12..15 (k bits)
#pragma unroll
    for (int qb = 0; qb < 4; qb++) bf_regs(a, qb, scA[qb], ssA[qb]);
    // D1 phase: e^{iA1} * e^{iB1[k]}
    const int c2 = t & 3;
#pragma unroll
    for (int k = 0; k < 16; k++) {
        const float2 pb = sB1[(k << 2) | c2];
        const float cr = pa.x * pb.x - pa.y * pb.y;
        const float ci = pa.x * pb.y + pa.y * pb.x;
        const float nx = a[k].x * cr - a[k].y * ci;
        const float ny = a[k].x * ci + a[k].y * cr;
        a[k] = make_float2(nx, ny);
    }
    // store psi1 (NO RY_B — conjugated into measurement)
#pragma unroll
    for (int k = 0; k < 16; k++) st[(k << 12) | low12] = a[k];
    // <X_q> for q12..15: register-pair cross terms (unordered pairs -> x2)
    float xs[4] = {0.f, 0.f, 0.f, 0.f};
#pragma unroll
    for (int qb = 0; qb < 4; qb++) {
#pragma unroll
        for (int p = 0; p < 8; p++) {
            const int j0 = ((p >> qb) << (qb + 1)) | (p & ((1 << qb) - 1));
            const int j1 = j0 | (1 << qb);
            xs[qb] += a[j0].x * a[j1].x + a[j0].y * a[j1].y;
        }
    }
#pragma unroll
    for (int qb = 0; qb < 4; qb++) xs[qb] = wsum(xs[qb]);
    if ((t & 31) == 0) {
#pragma unroll
        for (int qb = 0; qb < 4; qb++) wredX[t >> 5][qb] = xs[qb];
    }
    __syncthreads();
    if (t < 4) {
        float s = 0.f;
#pragma unroll
        for (int w2 = 0; w2 < 8; w2++) s += wredX[w2][t];
        g_X2[sim][blk][t] = 2.0f * s;
    }
}

// ---------------- K3: measurement only (Z_q and X_q on psi1) + fused final reduce ----------------
// Canonical layout: t bits = q0..7 (lane q0..4, warp q5..7), regs j = q8..11, tile = q12..15.
__global__ void __launch_bounds__(256) k_pass3(float* __restrict__ out) {
    const int sim = blockIdx.x >> 4;
    const int tile = blockIdx.x & 15;
    const int t = threadIdx.x;
    const int lane = t & 31;
    const int w = t >> 5;
    __shared__ float2 sbuf[4096];
    __shared__ float wred[8][22];
    __shared__ int sflag;
    const float2* stg = g_state + sim * SD + (tile << 12);
    float2 a[16];
#pragma unroll
    for (int j = 0; j < 16; j++) a[j] = stg[(j << 8) | t];

    // probs + Z for reg-bit qubits 8..11
    float pt = 0.f, z8 = 0.f, z9 = 0.f, z10 = 0.f, z11 = 0.f;
#pragma unroll
    for (int j = 0; j < 16; j++) {
        const float p = fmaf(a[j].y, a[j].y, a[j].x * a[j].x);
        pt += p;
        z8  += (j & 1) ? -p : p;
        z9  += (j & 2) ? -p : p;
        z10 += (j & 4) ? -p : p;
        z11 += (j & 8) ? -p : p;
    }
    // X for q8..11: register pairs (unordered -> x2 later)
    float xr[4] = {0.f, 0.f, 0.f, 0.f};
#pragma unroll
    for (int qb = 0; qb < 4; qb++) {
#pragma unroll
        for (int p = 0; p < 8; p++) {
            const int j0 = ((p >> qb) << (qb + 1)) | (p & ((1 << qb) - 1));
            const int j1 = j0 | (1 << qb);
            xr[qb] += a[j0].x * a[j1].x + a[j0].y * a[j1].y;
        }
    }
    // X for q0..4: lane-bit cross terms via shuffle (full sum over b, no x2)
    float xl[5];
#pragma unroll
    for (int q = 0; q < 5; q++) {
        const int m = 1 << q;
        float acc = 0.f;
#pragma unroll
        for (int j = 0; j < 16; j++) {
            const float ox = __shfl_xor_sync(0xffffffffu, a[j].x, m);
            const float oy = __shfl_xor_sync(0xffffffffu, a[j].y, m);
            acc += a[j].x * ox + a[j].y * oy;
        }
        xl[q] = acc;
    }
    // X for q5..7: cross-warp partners via one smem round (full sum, no x2)
#pragma unroll
    for (int j = 0; j < 16; j++) sbuf[(j << 8) | t] = a[j];
    __syncthreads();
    float xm[3];
#pragma unroll
    for (int qi = 0; qi < 3; qi++) {
        const int pt2 = t ^ (32 << qi);
        float acc = 0.f;
#pragma unroll
        for (int j = 0; j < 16; j++) {
            const float2 o = sbuf[(j << 8) | pt2];
            acc += a[j].x * o.x + a[j].y * o.y;
        }
        xm[qi] = acc;
    }

    // Walsh-Hadamard over the warp on pt: lane 0 -> sum, lane 2^q -> lane-signed Z_q part
    float v = pt;
#pragma unroll
    for (int st = 0; st < 5; st++) {
        const int m = 1 << st;
        const float o = __shfl_xor_sync(0xffffffffu, v, m);
        v = (lane & m) ? (o - v) : (v + o);
    }
    float Zl[5];
#pragma unroll
    for (int q = 0; q < 5; q++) Zl[q] = __shfl_sync(0xffffffffu, v, 1 << q);
    const float ptW = __shfl_sync(0xffffffffu, v, 0);

    // plain warp reductions: Z8..11, X0..11
    z8 = wsum(z8); z9 = wsum(z9); z10 = wsum(z10); z11 = wsum(z11);
#pragma unroll
    for (int q = 0; q < 5; q++) xl[q] = wsum(xl[q]);
#pragma unroll
    for (int q = 0; q < 3; q++) xm[q] = wsum(xm[q]);
#pragma unroll
    for (int q = 0; q < 4; q++) xr[q] = wsum(xr[q]);

    if (lane == 0) {
        wred[w][0] = ptW;
#pragma unroll
        for (int q = 0; q < 5; q++) wred[w][1 + q] = Zl[q];
        wred[w][6] = z8; wred[w][7] = z9; wred[w][8] = z10; wred[w][9] = z11;
#pragma unroll
        for (int q = 0; q < 5; q++) wred[w][10 + q] = xl[q];
#pragma unroll
        for (int q = 0; q < 3; q++) wred[w][15 + q] = xm[q];
#pragma unroll
        for (int q = 0; q < 4; q++) wred[w][18 + q] = 2.0f * xr[q];
    }
    __syncthreads();
    if (t < 16) {                       // Z partials
        const int q = t;
        float s = 0.f;
        if (q < 5) {
#pragma unroll
            for (int w2 = 0; w2 < 8; w2++) s += wred[w2][1 + q];
        } else if (q < 8) {
#pragma unroll
            for (int w2 = 0; w2 < 8; w2++)
                s += ((w2 >> (q - 5)) & 1) ? -wred[w2][0] : wred[w2][0];
        } else if (q < 12) {
#pragma unroll
            for (int w2 = 0; w2 < 8; w2++) s += wred[w2][6 + (q - 8)];
        } else {
            float tot = 0.f;
#pragma unroll
            for (int w2 = 0; w2 < 8; w2++) tot += wred[w2][0];
            s = ((tile >> (q - 12)) & 1) ? -tot : tot;
        }
        g_Z[sim][tile][q] = s;
    } else if (t < 28) {                // X partials q0..11
        const int q = t - 16;
        float s = 0.f;
#pragma unroll
        for (int w2 = 0; w2 < 8; w2++) s += wred[w2][10 + q];
        g_X[sim][tile][q] = s;
    }
    __syncthreads();
    if (t == 0) {
        __threadfence();
        const unsigned old = atomicAdd(&g_ctr, 1u);
        sflag = (old == (unsigned)(SIMS * 16 - 1));
    }
    __syncthreads();
    if (!sflag) return;

    // ---- final block: combine z_exp = cos(w1)*<Z> - sin(w1)*<X>, clip, permute ----
    __threadfence();
    for (int it = t; it < SIMS * 16; it += 256) {
        const int sim2 = it >> 4, q = it & 15;
        float Z = 0.f;
#pragma unroll
        for (int tl = 0; tl < 16; tl++) Z += g_Z[sim2][tl][q];
        float X = 0.f;
        if (q < 12) {
#pragma unroll
            for (int tl = 0; tl < 16; tl++) X += g_X[sim2][tl][q];
        } else {
#pragma unroll
            for (int b = 0; b < 16; b++) X += g_X2[sim2][b][q - 12];
        }
        float r = g_cw[q] * Z - g_sw[q] * X;
        r = fminf(1.0f, fmaxf(-1.0f, r));
        const int bb = sim2 >> 3, p = sim2 & 7, h = q >> 2, ww = q & 3;
        out[bb * 128 + h * 32 + p * 4 + ww] = r;
    }
}

// ---------------- launch ----------------
extern "C" void kernel_launch(void* const* d_in, const int* in_sizes, int n_in,
                              void* d_out, int out_size) {
    const float* x     = (const float*)d_in[0];
    const float* wcrz  = (const float*)d_in[1];
    const float* wry   = (const float*)d_in[2];
    const float* scale = (const float*)d_in[3];
    float* out = (float*)d_out;

    k_prep<<<SIMS + 4, 256>>>(x, wcrz, wry, scale);
    k_pass1<<<SIMS * 16, 256>>>();
    k_pass2<<<SIMS * 16, 256>>>();
    k_pass3<<<SIMS * 16, 256>>>(out);
}